// round 9
// baseline (speedup 1.0000x reference)
#include <cuda_runtime.h>
#include <math.h>

#define NN 50000
#define TT 1000
#define KL 5
#define KR 15
#define NC 5
#define PI_F 3.14159265358979323846f
#define MAXSLAB 128
#define MAXG 1024

typedef unsigned long long ull;

__device__ __forceinline__ ull pk2(float lo, float hi) {
    ull r; asm("mov.b64 %0,{%1,%2};" : "=l"(r) : "f"(lo), "f"(hi)); return r;
}
__device__ __forceinline__ float2 upk2(ull v) {
    float2 f; asm("mov.b64 {%0,%1},%2;" : "=f"(f.x), "=f"(f.y) : "l"(v)); return f;
}
__device__ __forceinline__ ull ffma2(ull a, ull b, ull c) {
    ull d; asm("fma.rn.f32x2 %0,%1,%2,%3;" : "=l"(d) : "l"(a), "l"(b), "l"(c)); return d;
}
__device__ __forceinline__ ull fmul2(ull a, ull b) {
    ull d; asm("mul.rn.f32x2 %0,%1,%2;" : "=l"(d) : "l"(a), "l"(b)); return d;
}

// packed 64B node rows: [float4 amp][float4 cos][float4 sin][pad]
__device__ float4 g_nd[NN * 4];
// per-block partial cluster sums: 65 floats each
__device__ float g_partial[MAXG * 65];
// finalized cluster stats: [0..19] meanAmp, [20..39] circPhase, [40..44] big
__device__ float g_cmeans[48];
__device__ unsigned g_cnt;            // barrier arrival counter (reset each launch)
__device__ volatile unsigned g_flag;  // barrier release ticket (monotonic)

__global__ __launch_bounds__(256, 4) void k_mega(
    const float* __restrict__ tv, const float* __restrict__ co,
    const float* __restrict__ lt, const float4* __restrict__ amp4,
    const float4* __restrict__ ph4, const float* __restrict__ lw,
    const float* __restrict__ rw, const int* __restrict__ li,
    const int* __restrict__ ri, const int* __restrict__ lab,
    float* __restrict__ out, int G)
{
    __shared__ union { float part[32 * 65]; ull pp[MAXSLAB * 18]; } sb;
    __shared__ ulonglong2 s_cp[MAXSLAB * 5];
    __shared__ float2 s_trig[TT];     // (sin, cos) of pi * t
    __shared__ float s_cm[48];
    __shared__ float s_cl[65];
    __shared__ float s_red[195];
    __shared__ unsigned s_last;

    int tid = threadIdx.x, bid = blockIdx.x;
    int wid = tid >> 5, lane = tid & 31;
    int start = (int)(((long long)bid * NN) / G);
    int end   = (int)(((long long)(bid + 1) * NN) / G);
    int nn = end - start;

    // ---- phase 1a: zero butterfly accumulator ----
    for (int i = tid; i < 32 * 65; i += 256) sb.part[i] = 0.f;
    __syncthreads();

    // ---- phase 1b: slab node table + cluster partials ----
    int passes = (nn + 255) >> 8;
    for (int p = 0; p < passes; p++) {
        int idx = (p << 8) + tid;
        int c = -1;
        float v[13];
        #pragma unroll
        for (int i = 0; i < 13; i++) v[i] = 0.f;
        if (idx < nn) {
            int gn = start + idx;
            float4 pp = ph4[gn];
            float4 a  = amp4[gn];
            float4 cs, sn;
            __sincosf(pp.x, &sn.x, &cs.x);
            __sincosf(pp.y, &sn.y, &cs.y);
            __sincosf(pp.z, &sn.z, &cs.z);
            __sincosf(pp.w, &sn.w, &cs.w);
            g_nd[gn * 4 + 0] = a;
            g_nd[gn * 4 + 1] = cs;
            g_nd[gn * 4 + 2] = sn;
            c = lab[gn];
            v[0] = 1.f;
            v[1] = a.x;  v[2] = a.y;  v[3] = a.z;  v[4] = a.w;
            v[5] = cs.x; v[6] = cs.y; v[7] = cs.z; v[8] = cs.w;
            v[9] = sn.x; v[10] = sn.y; v[11] = sn.z; v[12] = sn.w;
        }
        #pragma unroll
        for (int cc = 0; cc < NC; cc++) {
            #pragma unroll
            for (int i = 0; i < 13; i++) {
                float x = (c == cc) ? v[i] : 0.f;
                x += __shfl_xor_sync(0xffffffffu, x, 16);
                x += __shfl_xor_sync(0xffffffffu, x, 8);
                x += __shfl_xor_sync(0xffffffffu, x, 4);
                if (lane < 4) sb.part[(wid * 4 + lane) * 65 + cc * 13 + i] += x;
            }
        }
    }
    __syncthreads();
    if (tid < 65) {
        float s = 0.f;
        #pragma unroll
        for (int w = 0; w < 32; w++) s += sb.part[w * 65 + tid];
        g_partial[bid * 65 + tid] = s;
    }

    // ---- phase 1c: trig base table sin/cos(pi*t), accurate ----
    for (int i = tid; i < TT; i += 256) {
        float t = tv[i];
        float s, cq;
        sincosf(PI_F * t, &s, &cq);
        s_trig[i] = make_float2(s, cq);
    }

    __threadfence();
    __syncthreads();

    // ---- grid barrier (all G blocks co-resident by construction) ----
    unsigned tick = 0;
    if (tid == 0) {
        tick = g_flag;
        unsigned old = atomicAdd(&g_cnt, 1u);
        s_last = (old == (unsigned)(G - 1)) ? 1u : 0u;
    }
    __syncthreads();
    if (s_last) {
        __threadfence();
        if (tid < 195) {
            int v = tid % 65, ch = tid / 65;
            float s = 0.f;
            for (int r = ch; r < G; r += 3) s += g_partial[r * 65 + v];
            s_red[tid] = s;
        }
        __syncthreads();
        if (tid < 65) s_cl[tid] = s_red[tid] + s_red[65 + tid] + s_red[130 + tid];
        __syncthreads();
        if (tid < 20) {
            int cc = tid >> 2, i = tid & 3;
            float cnt = s_cl[cc * 13];
            g_cmeans[tid]      = s_cl[cc * 13 + 1 + i] / fmaxf(cnt, 1.f);
            g_cmeans[20 + tid] = atan2f(s_cl[cc * 13 + 9 + i], s_cl[cc * 13 + 5 + i]);
            if (i == 0) g_cmeans[40 + cc] = (cnt > 1.f) ? 1.f : 0.f;
        }
        __threadfence();
        __syncthreads();
        if (tid == 0) {
            g_cnt = 0;                       // reset for next launch/replay
            __threadfence();
            atomicAdd((unsigned*)&g_flag, 1u);
        }
    } else {
        if (tid == 0) {
            while (g_flag == tick) __nanosleep(64);
        }
        __syncthreads();
        __threadfence();
    }

    if (tid < 48) s_cm[tid] = g_cmeans[tid];

    const ulonglong2* ndA = (const ulonglong2*)g_nd;  // row j = ndA[j*4 + 0..2]

    // ---- phases A/B/C per sub-slab ----
    for (int sub = 0; sub < nn; sub += MAXSLAB) {
        int sn = min(MAXSLAB, nn - sub);

        // A: gather (3 roles per node: local | regional 0-7 | regional 8-14)
        __syncthreads();
        for (int i = tid; i < 3 * sn; i += 256) {
            int chunk = i / sn, node = i - chunk * sn;
            int gn = start + sub + node;
            ull r0 = 0, r1 = 0, r2 = 0, r3 = 0, r4 = 0, r5 = 0;
            if (chunk == 0) {
                #pragma unroll
                for (int k = 0; k < KL; k++) {
                    int j = li[gn * KL + k];
                    float w = lw[gn * KL + k];
                    ull wP = pk2(w, w);
                    ulonglong2 aj = ndA[j * 4 + 0];
                    ulonglong2 cj = ndA[j * 4 + 1];
                    ulonglong2 sj = ndA[j * 4 + 2];
                    r0 = ffma2(aj.x, wP, r0); r1 = ffma2(aj.y, wP, r1);
                    r2 = ffma2(cj.x, wP, r2); r3 = ffma2(cj.y, wP, r3);
                    r4 = ffma2(sj.x, wP, r4); r5 = ffma2(sj.y, wP, r5);
                }
            } else {
                int kb = (chunk == 1) ? 0 : 8;
                int ke = (chunk == 1) ? 8 : KR;
                for (int k = kb; k < ke; k++) {
                    int j = ri[gn * KR + k];
                    float w = rw[gn * KR + k];
                    ull wP = pk2(w, w);
                    ulonglong2 aj = ndA[j * 4 + 0];
                    ulonglong2 cj = ndA[j * 4 + 1];
                    ulonglong2 sj = ndA[j * 4 + 2];
                    r0 = ffma2(aj.x, wP, r0); r1 = ffma2(aj.y, wP, r1);
                    r2 = ffma2(cj.x, wP, r2); r3 = ffma2(cj.y, wP, r3);
                    r4 = ffma2(sj.x, wP, r4); r5 = ffma2(sj.y, wP, r5);
                }
            }
            ull* dst = &sb.pp[node * 18 + chunk * 6];
            dst[0] = r0; dst[1] = r1; dst[2] = r2;
            dst[3] = r3; dst[4] = r4; dst[5] = r5;
        }
        __syncthreads();

        // B: coefficients
        for (int node = tid; node < sn; node += 256) {
            int gn = start + sub + node;
            const ull* P = &sb.pp[node * 18];
            float la[4], lc[4], ls[4], ra[4], rc[4], rs[4];
            float2 x, y;
            x = upk2(P[0]); la[0] = x.x; la[1] = x.y;
            x = upk2(P[1]); la[2] = x.x; la[3] = x.y;
            x = upk2(P[2]); lc[0] = x.x; lc[1] = x.y;
            x = upk2(P[3]); lc[2] = x.x; lc[3] = x.y;
            x = upk2(P[4]); ls[0] = x.x; ls[1] = x.y;
            x = upk2(P[5]); ls[2] = x.x; ls[3] = x.y;
            x = upk2(P[6]);  y = upk2(P[12]); ra[0] = x.x + y.x; ra[1] = x.y + y.y;
            x = upk2(P[7]);  y = upk2(P[13]); ra[2] = x.x + y.x; ra[3] = x.y + y.y;
            x = upk2(P[8]);  y = upk2(P[14]); rc[0] = x.x + y.x; rc[1] = x.y + y.y;
            x = upk2(P[9]);  y = upk2(P[15]); rc[2] = x.x + y.x; rc[3] = x.y + y.y;
            x = upk2(P[10]); y = upk2(P[16]); rs[0] = x.x + y.x; rs[1] = x.y + y.y;
            x = upk2(P[11]); y = upk2(P[17]); rs[2] = x.x + y.x; rs[3] = x.y + y.y;

            float4 a4 = amp4[gn];
            float4 p4 = ph4[gn];
            float cov = co[gn], ltv = lt[gn];
            int c = lab[gn];
            bool big = s_cm[40 + c] > 0.5f;
            float aP[4] = {a4.x, a4.y, a4.z, a4.w};
            float pP[4] = {p4.x, p4.y, p4.z, p4.w};
            float av[4], bv[4];
            #pragma unroll
            for (int i = 0; i < 4; i++) {
                float campU = big ? s_cm[c * 4 + i] : aP[i];
                // combined = 0.5*local + 0.3*(0.7*regional_sum) + 0.2*cluster
                float ampO = 0.7f * aP[i] + 0.3f * (0.5f * la[i] + 0.21f * ra[i] + 0.2f * campU);
                float cphU = big ? s_cm[20 + c * 4 + i] : pP[i];
                float phL = atan2f(ls[i], lc[i]);
                float phR = atan2f(rs[i], rc[i]);
                float phO = 0.7f * pP[i] + 0.3f * (0.5f * phL + 0.3f * phR + 0.2f * cphU);
                float s, cc2;
                __sincosf(phO, &s, &cc2);
                av[i] = ampO * cc2;
                bv[i] = ampO * s;
            }
            ull* q = (ull*)&s_cp[node * 5];
            q[0] = pk2(cov, cov);     q[1] = pk2(ltv, ltv);
            q[2] = pk2(av[0], av[0]); q[3] = pk2(av[1], av[1]);
            q[4] = pk2(av[2], av[2]); q[5] = pk2(av[3], av[3]);
            q[6] = pk2(bv[0], bv[0]); q[7] = pk2(bv[1], bv[1]);
            q[8] = pk2(bv[2], bv[2]); q[9] = pk2(bv[3], bv[3]);
        }
        __syncthreads();

        // C: fill.  trig via 3 packed double-angle steps from sin/cos(pi*t)
        if (tid < 250) {
            int t0 = tid * 4;
            float4 tvv = ((const float4*)tv)[tid];
            ull T01 = pk2(tvv.x, tvv.y);
            ull T23 = pk2(tvv.z, tvv.w);
            float2 b0 = s_trig[t0], b1 = s_trig[t0 + 1];
            float2 b2 = s_trig[t0 + 2], b3 = s_trig[t0 + 3];
            ull TWO = pk2(2.f, 2.f), NTWO = pk2(-2.f, -2.f), ONE = pk2(1.f, 1.f);
            ull S01[4], C01[4], S23[4], C23[4];
            // index 3 = pi*t, 2 = 2pi*t, 1 = 4pi*t, 0 = 8pi*t
            S01[3] = pk2(b0.x, b1.x); C01[3] = pk2(b0.y, b1.y);
            S23[3] = pk2(b2.x, b3.x); C23[3] = pk2(b2.y, b3.y);
            #pragma unroll
            for (int lv = 3; lv > 0; lv--) {
                S01[lv-1] = fmul2(fmul2(TWO, S01[lv]), C01[lv]);
                C01[lv-1] = ffma2(fmul2(NTWO, S01[lv]), S01[lv], ONE);
                S23[lv-1] = fmul2(fmul2(TWO, S23[lv]), C23[lv]);
                C23[lv-1] = ffma2(fmul2(NTWO, S23[lv]), S23[lv], ONE);
            }

            #pragma unroll 2
            for (int j = 0; j < sn; j++) {
                ulonglong2 e0 = s_cp[j * 5 + 0];
                ulonglong2 e1 = s_cp[j * 5 + 1];
                ulonglong2 e2 = s_cp[j * 5 + 2];
                ulonglong2 e3 = s_cp[j * 5 + 3];
                ulonglong2 e4 = s_cp[j * 5 + 4];
                ull r0 = ffma2(e0.y, T01, e0.x);
                r0 = ffma2(e1.x, S01[0], r0); r0 = ffma2(e1.y, S01[1], r0);
                r0 = ffma2(e2.x, S01[2], r0); r0 = ffma2(e2.y, S01[3], r0);
                r0 = ffma2(e3.x, C01[0], r0); r0 = ffma2(e3.y, C01[1], r0);
                r0 = ffma2(e4.x, C01[2], r0); r0 = ffma2(e4.y, C01[3], r0);
                ull r1 = ffma2(e0.y, T23, e0.x);
                r1 = ffma2(e1.x, S23[0], r1); r1 = ffma2(e1.y, S23[1], r1);
                r1 = ffma2(e2.x, S23[2], r1); r1 = ffma2(e2.y, S23[3], r1);
                r1 = ffma2(e3.x, C23[0], r1); r1 = ffma2(e3.y, C23[1], r1);
                r1 = ffma2(e4.x, C23[2], r1); r1 = ffma2(e4.y, C23[3], r1);
                ulonglong2 o; o.x = r0; o.y = r1;
                *reinterpret_cast<ulonglong2*>(out + (size_t)(start + sub + j) * TT + t0) = o;
            }
        }
        __syncthreads();
    }
}

extern "C" void kernel_launch(void* const* d_in, const int* in_sizes, int n_in,
                              void* d_out, int out_size) {
    const float* tv  = (const float*)d_in[0];  // time_vector        [1000]
    const float* co  = (const float*)d_in[1];  // constant_offset    [50000]
    const float* lt  = (const float*)d_in[2];  // linear_trend       [50000]
    const float* amp = (const float*)d_in[3];  // seasonal_amplitudes[50000,4]
    const float* ph  = (const float*)d_in[4];  // seasonal_phases    [50000,4]
    const float* lw  = (const float*)d_in[5];  // local_w            [50000,5]
    const float* rw  = (const float*)d_in[6];  // regional_w         [50000,15]
    const int*   li  = (const int*)d_in[7];    // local_idx          [50000,5]
    const int*   ri  = (const int*)d_in[8];    // regional_idx       [50000,15]
    const int*   lab = (const int*)d_in[9];    // cluster_labels     [50000]
    float* out = (float*)d_out;

    // Grid sized so ALL blocks are co-resident (required by the spin barrier).
    int sms = 148;
    cudaDeviceGetAttribute(&sms, cudaDevAttrMultiProcessorCount, 0);
    int occ = 4;
    cudaOccupancyMaxActiveBlocksPerMultiprocessor(&occ, k_mega, 256, 0);
    if (occ > 4) occ = 4;
    if (occ < 1) occ = 1;
    int G = sms * occ;
    if (G > MAXG) G = MAXG;

    k_mega<<<G, 256>>>(tv, co, lt, (const float4*)amp, (const float4*)ph,
                       lw, rw, li, ri, lab, out, G);
}

// round 11
// speedup vs baseline: 1.0908x; 1.0908x over previous
#include <cuda_runtime.h>
#include <math.h>

#define NN 50000
#define TT 1000
#define KL 5
#define KR 15
#define NC 5
#define PI_F 3.14159265358979323846f
#define PREG 148
#define PRETHR 512
#define GRIDF 592
#define MAXSLAB 85

typedef unsigned long long ull;

__device__ __forceinline__ ull pk2(float lo, float hi) {
    ull r; asm("mov.b64 %0,{%1,%2};" : "=l"(r) : "f"(lo), "f"(hi)); return r;
}
__device__ __forceinline__ float2 upk2(ull v) {
    float2 f; asm("mov.b64 {%0,%1},%2;" : "=f"(f.x), "=f"(f.y) : "l"(v)); return f;
}
__device__ __forceinline__ ull ffma2(ull a, ull b, ull c) {
    ull d; asm("fma.rn.f32x2 %0,%1,%2,%3;" : "=l"(d) : "l"(a), "l"(b), "l"(c)); return d;
}
__device__ __forceinline__ ull fmul2(ull a, ull b) {
    ull d; asm("mul.rn.f32x2 %0,%1,%2;" : "=l"(d) : "l"(a), "l"(b)); return d;
}

// packed 64B node rows: [float4 amp][float4 cos][float4 sin][pad]
__device__ float4 g_nd[NN * 4];
// per-block partial cluster sums: [count, sumAmp*4, sumCos*4, sumSin*4] x NC
__device__ float g_partial[PREG * 65];
// finalized cluster stats: [0..19] meanAmp, [20..39] circPhase, [40..44] big flag
__device__ float g_cmeans[48];
__device__ unsigned g_arr;  // arrival counter; reset by last block each launch

// ---------------------------------------------------------------------------
// Stage 1: per-node sincos -> packed fp32 node table; per-block cluster
// partials via 3-step warp butterfly; LAST block reduces to g_cmeans.
// Deterministic (fixed-order reductions), replay-safe (counter reset).
// ---------------------------------------------------------------------------
__global__ __launch_bounds__(PRETHR) void k_pre(const float4* __restrict__ amp,
                                                const float4* __restrict__ ph,
                                                const int* __restrict__ lab) {
    __shared__ float s_part[64 * 65];   // 16 warps x 4 residue rows
    __shared__ float s_cl[65];
    __shared__ unsigned s_last;
    int tid = threadIdx.x;
    int wid = tid >> 5, lane = tid & 31;
    int n = blockIdx.x * PRETHR + tid;

    float v[13];
    int c = -1;
    if (n < NN) {
        float4 p = ph[n];
        float4 cs, sn;
        __sincosf(p.x, &sn.x, &cs.x);
        __sincosf(p.y, &sn.y, &cs.y);
        __sincosf(p.z, &sn.z, &cs.z);
        __sincosf(p.w, &sn.w, &cs.w);
        float4 a = amp[n];
        g_nd[n * 4 + 0] = a;
        g_nd[n * 4 + 1] = cs;
        g_nd[n * 4 + 2] = sn;
        c = lab[n];
        v[0] = 1.f;
        v[1] = a.x;  v[2] = a.y;  v[3] = a.z;  v[4] = a.w;
        v[5] = cs.x; v[6] = cs.y; v[7] = cs.z; v[8] = cs.w;
        v[9] = sn.x; v[10] = sn.y; v[11] = sn.z; v[12] = sn.w;
    } else {
        #pragma unroll
        for (int i = 0; i < 13; i++) v[i] = 0.f;
    }

    #pragma unroll
    for (int cc = 0; cc < NC; cc++) {
        #pragma unroll
        for (int i = 0; i < 13; i++) {
            float x = (c == cc) ? v[i] : 0.f;
            x += __shfl_xor_sync(0xffffffffu, x, 16);
            x += __shfl_xor_sync(0xffffffffu, x, 8);
            x += __shfl_xor_sync(0xffffffffu, x, 4);
            if (lane < 4) s_part[(wid * 4 + lane) * 65 + cc * 13 + i] = x;
        }
    }
    __syncthreads();
    if (tid < 65) {
        float s = 0.f;
        #pragma unroll
        for (int w = 0; w < 64; w++) s += s_part[w * 65 + tid];
        g_partial[blockIdx.x * 65 + tid] = s;
    }
    __threadfence();
    __syncthreads();
    if (tid == 0) {
        unsigned o = atomicAdd(&g_arr, 1u);
        s_last = (o == PREG - 1) ? 1u : 0u;
    }
    __syncthreads();
    if (s_last) {
        __threadfence();
        if (tid < 65) {
            float s = 0.f;
            for (int r = 0; r < PREG; r++) s += g_partial[r * 65 + tid];
            s_cl[tid] = s;
        }
        __syncthreads();
        if (tid < 20) {
            int cc = tid >> 2, i = tid & 3;
            float cnt = s_cl[cc * 13];
            g_cmeans[tid]      = s_cl[cc * 13 + 1 + i] / fmaxf(cnt, 1.f);
            g_cmeans[20 + tid] = atan2f(s_cl[cc * 13 + 9 + i], s_cl[cc * 13 + 5 + i]);
            if (i == 0) g_cmeans[40 + cc] = (cnt > 1.f) ? 1.f : 0.f;
        }
        if (tid == 0) g_arr = 0u;   // reset for next graph replay
    }
}

// ---------------------------------------------------------------------------
// Stage 2 (fused coef + fill). Block b owns slab of <=85 nodes.
//   phase 0: build s_trig[1000] = sincos(pi*t) (4 sincosf/thread, overlaps
//            the gather's LDG latency in phase A issue order).
//   phase A: 3 threads per node gather (local | regional 0-7 | regional 8-14).
//   phase B: owner thread -> packed coefficients in shared.
//   phase C: fill; per-thread trig from s_trig via 3 exact double-angle steps.
// ---------------------------------------------------------------------------
__global__ __launch_bounds__(256, 4) void k_fused(const float* __restrict__ tv,
                                                  const float* __restrict__ co,
                                                  const float* __restrict__ lt,
                                                  const float* __restrict__ amp,
                                                  const float* __restrict__ ph,
                                                  const float* __restrict__ lw,
                                                  const float* __restrict__ rw,
                                                  const int* __restrict__ li,
                                                  const int* __restrict__ ri,
                                                  const int* __restrict__ lab,
                                                  float* __restrict__ out) {
    __shared__ float s_cm[48];
    __shared__ ull s_pp[MAXSLAB * 12];       // chunk1/2 regional partials
    __shared__ ulonglong2 s_cp[MAXSLAB * 5]; // dup-packed coefficients
    __shared__ float2 s_trig[TT];            // (sin, cos)(pi * t)
    int tid = threadIdx.x;
    int start = (int)(((long long)blockIdx.x * NN) / GRIDF);
    int end   = (int)(((long long)(blockIdx.x + 1) * NN) / GRIDF);
    int nn = end - start;

    if (tid < 48) s_cm[tid] = g_cmeans[tid];

    // phase 0: trig base table (accurate)
    for (int i = tid; i < TT; i += 256) {
        float t = tv[i];
        float s, cq;
        sincosf(PI_F * t, &s, &cq);
        s_trig[i] = make_float2(s, cq);
    }

    int node = -1, chunk = 0;
    if (tid < nn)          { node = tid;          chunk = 0; }
    else if (tid < 2 * nn) { node = tid - nn;     chunk = 1; }
    else if (tid < 3 * nn) { node = tid - 2 * nn; chunk = 2; }

    const ulonglong2* ndA = (const ulonglong2*)g_nd;  // row j = ndA[j*4 + 0..2]

    // owner-persistent state
    ull la01 = 0, la23 = 0, lc01 = 0, lc23 = 0, ls01 = 0, ls23 = 0;
    float4 a4, p4;
    float cov = 0.f, ltv = 0.f;
    int c = 0;

    if (node >= 0) {
        int gn = start + node;
        if (chunk == 0) {
            a4 = ((const float4*)amp)[gn];
            p4 = ((const float4*)ph)[gn];
            cov = co[gn]; ltv = lt[gn]; c = lab[gn];
            #pragma unroll
            for (int k = 0; k < KL; k++) {
                int j = li[gn * KL + k];
                float w = lw[gn * KL + k];
                ull wP = pk2(w, w);
                ulonglong2 aj = ndA[j * 4 + 0];
                ulonglong2 cj = ndA[j * 4 + 1];
                ulonglong2 sj = ndA[j * 4 + 2];
                la01 = ffma2(aj.x, wP, la01); la23 = ffma2(aj.y, wP, la23);
                lc01 = ffma2(cj.x, wP, lc01); lc23 = ffma2(cj.y, wP, lc23);
                ls01 = ffma2(sj.x, wP, ls01); ls23 = ffma2(sj.y, wP, ls23);
            }
        } else {
            int kb = (chunk == 1) ? 0 : 8;
            int ke = (chunk == 1) ? 8 : KR;
            ull r0 = 0, r1 = 0, r2 = 0, r3 = 0, r4 = 0, r5 = 0;
            for (int k = kb; k < ke; k++) {
                int j = ri[gn * KR + k];
                float w = rw[gn * KR + k];
                ull wP = pk2(w, w);
                ulonglong2 aj = ndA[j * 4 + 0];
                ulonglong2 cj = ndA[j * 4 + 1];
                ulonglong2 sj = ndA[j * 4 + 2];
                r0 = ffma2(aj.x, wP, r0); r1 = ffma2(aj.y, wP, r1);
                r2 = ffma2(cj.x, wP, r2); r3 = ffma2(cj.y, wP, r3);
                r4 = ffma2(sj.x, wP, r4); r5 = ffma2(sj.y, wP, r5);
            }
            ull* dst = &s_pp[node * 12 + (chunk - 1) * 6];
            dst[0] = r0; dst[1] = r1; dst[2] = r2;
            dst[3] = r3; dst[4] = r4; dst[5] = r5;
        }
    }
    __syncthreads();

    if (node >= 0 && chunk == 0) {
        // merge regional partials
        float ra[4], rc[4], rs[4];
        {
            const ull* p1 = &s_pp[node * 12];
            const ull* p2 = p1 + 6;
            float2 x, y;
            x = upk2(p1[0]); y = upk2(p2[0]); ra[0] = x.x + y.x; ra[1] = x.y + y.y;
            x = upk2(p1[1]); y = upk2(p2[1]); ra[2] = x.x + y.x; ra[3] = x.y + y.y;
            x = upk2(p1[2]); y = upk2(p2[2]); rc[0] = x.x + y.x; rc[1] = x.y + y.y;
            x = upk2(p1[3]); y = upk2(p2[3]); rc[2] = x.x + y.x; rc[3] = x.y + y.y;
            x = upk2(p1[4]); y = upk2(p2[4]); rs[0] = x.x + y.x; rs[1] = x.y + y.y;
            x = upk2(p1[5]); y = upk2(p2[5]); rs[2] = x.x + y.x; rs[3] = x.y + y.y;
        }
        float la[4], lc[4], ls[4];
        float2 t;
        t = upk2(la01); la[0] = t.x; la[1] = t.y;  t = upk2(la23); la[2] = t.x; la[3] = t.y;
        t = upk2(lc01); lc[0] = t.x; lc[1] = t.y;  t = upk2(lc23); lc[2] = t.x; lc[3] = t.y;
        t = upk2(ls01); ls[0] = t.x; ls[1] = t.y;  t = upk2(ls23); ls[2] = t.x; ls[3] = t.y;

        bool big = s_cm[40 + c] > 0.5f;
        float aP[4] = {a4.x, a4.y, a4.z, a4.w};
        float pP[4] = {p4.x, p4.y, p4.z, p4.w};
        float av[4], bv[4];
        #pragma unroll
        for (int i = 0; i < 4; i++) {
            float campU = big ? s_cm[c * 4 + i] : aP[i];
            // combined = 0.5*local + 0.3*(0.7*regional_sum) + 0.2*cluster
            float ampO = 0.7f * aP[i] + 0.3f * (0.5f * la[i] + 0.21f * ra[i] + 0.2f * campU);
            float cphU = big ? s_cm[20 + c * 4 + i] : pP[i];
            float phL = atan2f(ls[i], lc[i]);
            float phR = atan2f(rs[i], rc[i]);
            float phO = 0.7f * pP[i] + 0.3f * (0.5f * phL + 0.3f * phR + 0.2f * cphU);
            float s, cc2;
            __sincosf(phO, &s, &cc2);
            av[i] = ampO * cc2;
            bv[i] = ampO * s;
        }
        ull* q = (ull*)&s_cp[node * 5];
        q[0] = pk2(cov, cov);     q[1] = pk2(ltv, ltv);
        q[2] = pk2(av[0], av[0]); q[3] = pk2(av[1], av[1]);
        q[4] = pk2(av[2], av[2]); q[5] = pk2(av[3], av[3]);
        q[6] = pk2(bv[0], bv[0]); q[7] = pk2(bv[1], bv[1]);
        q[8] = pk2(bv[2], bv[2]); q[9] = pk2(bv[3], bv[3]);
    }
    __syncthreads();

    int t0 = tid * 4;
    if (t0 >= TT) return;  // threads 250..255 already did their shared-memory duty

    float4 tvv = ((const float4*)tv)[tid];
    ull T01 = pk2(tvv.x, tvv.y);
    ull T23 = pk2(tvv.z, tvv.w);

    // trig from table via 3 exact double-angle steps:
    // index 3 = pi*t (period 2), 2 = 2pi*t (period 1), 1 = 4pi*t, 0 = 8pi*t
    float2 b0 = s_trig[t0], b1 = s_trig[t0 + 1];
    float2 b2 = s_trig[t0 + 2], b3 = s_trig[t0 + 3];
    ull TWO = pk2(2.f, 2.f), NTWO = pk2(-2.f, -2.f), ONE = pk2(1.f, 1.f);
    ull S01[4], C01[4], S23[4], C23[4];
    S01[3] = pk2(b0.x, b1.x); C01[3] = pk2(b0.y, b1.y);
    S23[3] = pk2(b2.x, b3.x); C23[3] = pk2(b2.y, b3.y);
    #pragma unroll
    for (int lv = 3; lv > 0; lv--) {
        S01[lv-1] = fmul2(fmul2(TWO, S01[lv]), C01[lv]);
        C01[lv-1] = ffma2(fmul2(NTWO, S01[lv]), S01[lv], ONE);
        S23[lv-1] = fmul2(fmul2(TWO, S23[lv]), C23[lv]);
        C23[lv-1] = ffma2(fmul2(NTWO, S23[lv]), S23[lv], ONE);
    }

    #pragma unroll 2
    for (int j = 0; j < nn; j++) {
        ulonglong2 e0 = s_cp[j * 5 + 0];
        ulonglong2 e1 = s_cp[j * 5 + 1];
        ulonglong2 e2 = s_cp[j * 5 + 2];
        ulonglong2 e3 = s_cp[j * 5 + 3];
        ulonglong2 e4 = s_cp[j * 5 + 4];
        ull r0 = ffma2(e0.y, T01, e0.x);
        r0 = ffma2(e1.x, S01[0], r0); r0 = ffma2(e1.y, S01[1], r0);
        r0 = ffma2(e2.x, S01[2], r0); r0 = ffma2(e2.y, S01[3], r0);
        r0 = ffma2(e3.x, C01[0], r0); r0 = ffma2(e3.y, C01[1], r0);
        r0 = ffma2(e4.x, C01[2], r0); r0 = ffma2(e4.y, C01[3], r0);
        ull r1 = ffma2(e0.y, T23, e0.x);
        r1 = ffma2(e1.x, S23[0], r1); r1 = ffma2(e1.y, S23[1], r1);
        r1 = ffma2(e2.x, S23[2], r1); r1 = ffma2(e2.y, S23[3], r1);
        r1 = ffma2(e3.x, C23[0], r1); r1 = ffma2(e3.y, C23[1], r1);
        r1 = ffma2(e4.x, C23[2], r1); r1 = ffma2(e4.y, C23[3], r1);
        ulonglong2 o; o.x = r0; o.y = r1;
        *reinterpret_cast<ulonglong2*>(out + (size_t)(start + j) * TT + t0) = o;
    }
}

extern "C" void kernel_launch(void* const* d_in, const int* in_sizes, int n_in,
                              void* d_out, int out_size) {
    const float* tv  = (const float*)d_in[0];  // time_vector        [1000]
    const float* co  = (const float*)d_in[1];  // constant_offset    [50000]
    const float* lt  = (const float*)d_in[2];  // linear_trend       [50000]
    const float* amp = (const float*)d_in[3];  // seasonal_amplitudes[50000,4]
    const float* ph  = (const float*)d_in[4];  // seasonal_phases    [50000,4]
    const float* lw  = (const float*)d_in[5];  // local_w            [50000,5]
    const float* rw  = (const float*)d_in[6];  // regional_w         [50000,15]
    const int*   li  = (const int*)d_in[7];    // local_idx          [50000,5]
    const int*   ri  = (const int*)d_in[8];    // regional_idx       [50000,15]
    const int*   lab = (const int*)d_in[9];    // cluster_labels     [50000]
    float* out = (float*)d_out;

    k_pre<<<PREG, PRETHR>>>((const float4*)amp, (const float4*)ph, lab);
    k_fused<<<GRIDF, 256>>>(tv, co, lt, amp, ph, lw, rw, li, ri, lab, out);
}